// round 3
// baseline (speedup 1.0000x reference)
#include <cuda_runtime.h>
#include <cuda_bf16.h>
#include <mma.h>

using namespace nvcuda;
typedef __nv_bfloat16 bf16;

#define BM 128
#define BN 64
#define BK 32
#define AP 40   // As leading dim (bf16 elems): 80B, 16B-aligned rows
#define BPV 40  // vocab Bs[n][k] ld
#define BPP 72  // proj Bs[k][n] ld (144B, mult of 16B)
#define CP 68   // epilogue fp32 tile ld (272B, mult of 16B)

#define OFF_H0 0
#define OFF_H1 1048576            // 1024*1024
#define OFF_H2 1310720            // +1024*256
#define OFF_H3 1376256            // +1024*64

// scratch (static device memory; no allocations anywhere)
__device__ bf16  g_H[1392640];
__device__ float g_sumexp[4096];

__global__ void zero_kernel() {
    int i = blockIdx.x * blockDim.x + threadIdx.x;
    if (i < 4096) g_sumexp[i] = 0.0f;
}

// ---------------------------------------------------------------------------
// Projection GEMM: H[m,n] = sum_k hidden[m,k] * proj[k,n]; write bf16 to g_H
// A fp32 [1024, 1024], B fp32 [1024, Nout] row-major. K = 1024 always.
// ---------------------------------------------------------------------------
__global__ __launch_bounds__(256) void proj_kernel(const float* __restrict__ A,
                                                   const float* __restrict__ B,
                                                   int Nout, int h_off)
{
    __shared__ __align__(16) float s_c[BM * CP];
    bf16* As = (bf16*)s_c;
    bf16* Bs = As + BM * AP;

    const int tid = threadIdx.x;
    const int warpId = tid >> 5;
    const int wm = warpId & 3, wn = warpId >> 2;
    const int m0 = blockIdx.y * BM;
    const int n0 = blockIdx.x * BN;
    const int K = 1024;

    wmma::fragment<wmma::accumulator, 16, 16, 16, float> acc[2][2];
    #pragma unroll
    for (int i = 0; i < 2; i++)
        #pragma unroll
        for (int j = 0; j < 2; j++) wmma::fill_fragment(acc[i][j], 0.0f);

    for (int kt = 0; kt < K; kt += BK) {
        // A tile: BM*BK fp32 = 1024 float4, 4 per thread
        #pragma unroll
        for (int i = 0; i < 4; i++) {
            int idx = tid + i * 256;
            int r = idx >> 3, kq = (idx & 7) << 2;
            float4 v = *(const float4*)(A + (size_t)(m0 + r) * K + kt + kq);
            bf16* d = As + r * AP + kq;
            d[0] = __float2bfloat16(v.x); d[1] = __float2bfloat16(v.y);
            d[2] = __float2bfloat16(v.z); d[3] = __float2bfloat16(v.w);
        }
        // B tile: BK*BN fp32 = 512 float4, 2 per thread; Bs[k][n]
        #pragma unroll
        for (int i = 0; i < 2; i++) {
            int idx = tid + i * 256;
            int kr = idx >> 4, nq = (idx & 15) << 2;
            int n = n0 + nq;
            float4 v = make_float4(0.f, 0.f, 0.f, 0.f);
            if (n < Nout) v = *(const float4*)(B + (size_t)(kt + kr) * Nout + n);
            bf16* d = Bs + kr * BPP + nq;
            d[0] = __float2bfloat16(v.x); d[1] = __float2bfloat16(v.y);
            d[2] = __float2bfloat16(v.z); d[3] = __float2bfloat16(v.w);
        }
        __syncthreads();
        #pragma unroll
        for (int kk = 0; kk < BK; kk += 16) {
            wmma::fragment<wmma::matrix_a, 16, 16, 16, bf16, wmma::row_major> af[2];
            wmma::fragment<wmma::matrix_b, 16, 16, 16, bf16, wmma::row_major> bfr[2];
            #pragma unroll
            for (int i = 0; i < 2; i++)
                wmma::load_matrix_sync(af[i], As + (wm * 32 + i * 16) * AP + kk, AP);
            #pragma unroll
            for (int j = 0; j < 2; j++)
                wmma::load_matrix_sync(bfr[j], Bs + kk * BPP + wn * 32 + j * 16, BPP);
            #pragma unroll
            for (int i = 0; i < 2; i++)
                #pragma unroll
                for (int j = 0; j < 2; j++)
                    wmma::mma_sync(acc[i][j], af[i], bfr[j], acc[i][j]);
        }
        __syncthreads();
    }

    #pragma unroll
    for (int i = 0; i < 2; i++)
        #pragma unroll
        for (int j = 0; j < 2; j++)
            wmma::store_matrix_sync(s_c + (wm * 32 + i * 16) * CP + wn * 32 + j * 16,
                                    acc[i][j], CP, wmma::mem_row_major);
    __syncthreads();

    bf16* H = g_H + h_off;
    for (int idx = tid; idx < BM * BN; idx += 256) {
        int r = idx >> 6, c = idx & 63;
        int n = n0 + c;
        if (n < Nout)
            H[(size_t)(m0 + r) * Nout + n] = __float2bfloat16(s_c[r * CP + c]);
    }
}

// ---------------------------------------------------------------------------
// Vocab GEMM + fused exp-sum: sumexp[c][m] += sum_v exp(H[m,:] . W[v,:] + b[v])
// H bf16 [1024, K] in g_H; W fp32 [V, K] row-major (rows >= split from W2).
// ---------------------------------------------------------------------------
__global__ __launch_bounds__(256) void vocab_kernel(int h_off, int K,
        const float* __restrict__ W,  const float* __restrict__ W2,
        const float* __restrict__ bias, const float* __restrict__ bias2,
        int split, int V, int cidx)
{
    __shared__ __align__(16) float s_c[BM * CP];
    bf16* As = (bf16*)s_c;
    bf16* Bs = As + BM * AP;

    const bf16* __restrict__ H = g_H + h_off;
    const int tid = threadIdx.x;
    const int warpId = tid >> 5, lane = tid & 31;
    const int wm = warpId & 3, wn = warpId >> 2;
    const int m0 = blockIdx.y * BM;
    const int n0 = blockIdx.x * BN;

    wmma::fragment<wmma::accumulator, 16, 16, 16, float> acc[2][2];
    #pragma unroll
    for (int i = 0; i < 2; i++)
        #pragma unroll
        for (int j = 0; j < 2; j++) wmma::fill_fragment(acc[i][j], 0.0f);

    for (int kt = 0; kt < K; kt += BK) {
        // A tile: BM*BK bf16 = 128 rows x 32 cols = 512 uint4 (8 bf16 each),
        // 4 uint4 per row, 2 per thread.  (Round-2 fix: r=idx>>2, kq=(idx&3)<<3)
        #pragma unroll
        for (int i = 0; i < 2; i++) {
            int idx = tid + i * 256;
            int r = idx >> 2, kq = (idx & 3) << 3;
            uint4 v = make_uint4(0u, 0u, 0u, 0u);
            if (kt + kq < K) v = *(const uint4*)(H + (size_t)(m0 + r) * K + kt + kq);
            *(uint4*)(As + r * AP + kq) = v;
        }
        // B tile: BN*BK fp32 = 512 float4, 2 per thread; Bs[n][k]
        #pragma unroll
        for (int i = 0; i < 2; i++) {
            int idx = tid + i * 256;
            int r = idx >> 3, kq = (idx & 7) << 2;
            int v = n0 + r;
            float4 val = make_float4(0.f, 0.f, 0.f, 0.f);
            if (v < V && kt + kq < K) {
                const float* wr = (v < split) ? (W + (size_t)v * K)
                                              : (W2 + (size_t)(v - split) * K);
                val = *(const float4*)(wr + kt + kq);
            }
            bf16* d = Bs + r * BPV + kq;
            d[0] = __float2bfloat16(val.x); d[1] = __float2bfloat16(val.y);
            d[2] = __float2bfloat16(val.z); d[3] = __float2bfloat16(val.w);
        }
        __syncthreads();
        #pragma unroll
        for (int kk = 0; kk < BK; kk += 16) {
            wmma::fragment<wmma::matrix_a, 16, 16, 16, bf16, wmma::row_major> af[2];
            wmma::fragment<wmma::matrix_b, 16, 16, 16, bf16, wmma::col_major> bfr[2];
            #pragma unroll
            for (int i = 0; i < 2; i++)
                wmma::load_matrix_sync(af[i], As + (wm * 32 + i * 16) * AP + kk, AP);
            #pragma unroll
            for (int j = 0; j < 2; j++)
                wmma::load_matrix_sync(bfr[j], Bs + (wn * 32 + j * 16) * BPV + kk, BPV);
            #pragma unroll
            for (int i = 0; i < 2; i++)
                #pragma unroll
                for (int j = 0; j < 2; j++)
                    wmma::mma_sync(acc[i][j], af[i], bfr[j], acc[i][j]);
        }
        __syncthreads();
    }

    #pragma unroll
    for (int i = 0; i < 2; i++)
        #pragma unroll
        for (int j = 0; j < 2; j++)
            wmma::store_matrix_sync(s_c + (wm * 32 + i * 16) * CP + wn * 32 + j * 16,
                                    acc[i][j], CP, wmma::mem_row_major);
    __syncthreads();

    // fused exp + per-row sum: warp w handles rows w, w+8, ...
    for (int r = warpId; r < BM; r += 8) {
        float s = 0.0f;
        #pragma unroll
        for (int cc = 0; cc < 2; cc++) {
            int c = lane + cc * 32;
            int v = n0 + c;
            if (v < V) {
                float bb = (v < split) ? bias[v] : bias2[v - split];
                s += __expf(s_c[r * CP + c] + bb);
            }
        }
        #pragma unroll
        for (int o = 16; o; o >>= 1) s += __shfl_xor_sync(0xffffffffu, s, o);
        if (lane == 0) atomicAdd(&g_sumexp[cidx * 1024 + m0 + r], s);
    }
}

// ---------------------------------------------------------------------------
// Finalize: per-row target logit (exact dot from bf16 H, fp32 W) + combine.
// One warp per row.
// ---------------------------------------------------------------------------
__device__ __forceinline__ float wdot(const bf16* h, const float* w, int K, int lane) {
    float s = 0.0f;
    for (int k = lane; k < K; k += 32)
        s += __bfloat162float(h[k]) * w[k];
    #pragma unroll
    for (int o = 16; o; o >>= 1) s += __shfl_xor_sync(0xffffffffu, s, o);
    return s;
}

__global__ __launch_bounds__(256) void finalize_kernel(const int* __restrict__ target,
    const float* __restrict__ head_w,   const float* __restrict__ head_b,
    const float* __restrict__ cluster_w, const float* __restrict__ cluster_b,
    const float* __restrict__ w1, const float* __restrict__ b1,
    const float* __restrict__ w2, const float* __restrict__ b2,
    const float* __restrict__ w3, const float* __restrict__ b3,
    float* __restrict__ out)
{
    int warpId = threadIdx.x >> 5, lane = threadIdx.x & 31;
    int row = blockIdx.x * 8 + warpId;
    if (row >= 1024) return;

    const bf16* h0 = g_H + (size_t)row * 1024;

    float cl[3];
    #pragma unroll
    for (int j = 0; j < 3; j++)
        cl[j] = wdot(h0, cluster_w + j * 1024, 1024, lane) + cluster_b[j];

    float lse0 = logf(g_sumexp[row]);
    int t = target[row];
    float lp;
    if (t < 20000) {
        float s = wdot(h0, head_w + (size_t)t * 1024, 1024, lane) + head_b[t];
        lp = s - lse0;
    } else if (t < 40000) {
        int ti = t - 20000;
        const bf16* h = g_H + OFF_H1 + (size_t)row * 256;
        float s = wdot(h, w1 + (size_t)ti * 256, 256, lane) + b1[ti];
        lp = (cl[2] - lse0) + (s - logf(g_sumexp[1024 + row]));
    } else if (t < 200000) {
        int ti = t - 40000;
        const bf16* h = g_H + OFF_H2 + (size_t)row * 64;
        float s = wdot(h, w2 + (size_t)ti * 64, 64, lane) + b2[ti];
        lp = (cl[1] - lse0) + (s - logf(g_sumexp[2048 + row]));
    } else {
        int ti = t - 200000;
        const bf16* h = g_H + OFF_H3 + (size_t)row * 16;
        float s = wdot(h, w3 + (size_t)ti * 16, 16, lane) + b3[ti];
        lp = (cl[0] - lse0) + (s - logf(g_sumexp[3072 + row]));
    }
    if (lane == 0) out[row] = -lp;
}

// ---------------------------------------------------------------------------
extern "C" void kernel_launch(void* const* d_in, const int* in_sizes, int n_in,
                              void* d_out, int out_size)
{
    const float* hidden    = (const float*)d_in[0];
    const int*   target    = (const int*)  d_in[1];
    const float* head_w    = (const float*)d_in[2];
    const float* head_b    = (const float*)d_in[3];
    const float* cluster_w = (const float*)d_in[4];
    const float* cluster_b = (const float*)d_in[5];
    const float* proj0     = (const float*)d_in[6];
    const float* proj1     = (const float*)d_in[7];
    const float* proj2     = (const float*)d_in[8];
    const float* proj3     = (const float*)d_in[9];
    const float* w1        = (const float*)d_in[10];
    const float* b1        = (const float*)d_in[11];
    const float* w2        = (const float*)d_in[12];
    const float* b2        = (const float*)d_in[13];
    const float* w3        = (const float*)d_in[14];
    const float* b3        = (const float*)d_in[15];
    float* out = (float*)d_out;

    dim3 blk(256);
    zero_kernel<<<16, 256>>>();

    proj_kernel<<<dim3(16, 8), blk>>>(hidden, proj0, 1024, OFF_H0);
    proj_kernel<<<dim3(4, 8),  blk>>>(hidden, proj1, 256,  OFF_H1);
    proj_kernel<<<dim3(1, 8),  blk>>>(hidden, proj2, 64,   OFF_H2);
    proj_kernel<<<dim3(1, 8),  blk>>>(hidden, proj3, 16,   OFF_H3);

    // head: 20000 shortlist rows + 3 cluster rows, V = 20003
    vocab_kernel<<<dim3(313, 8),  blk>>>(OFF_H0, 1024, head_w, cluster_w,
                                         head_b, cluster_b, 20000, 20003, 0);
    vocab_kernel<<<dim3(313, 8),  blk>>>(OFF_H1, 256, w1, w1, b1, b1,
                                         20000, 20000, 1);
    vocab_kernel<<<dim3(2500, 8), blk>>>(OFF_H2, 64, w2, w2, b2, b2,
                                         160000, 160000, 2);
    vocab_kernel<<<dim3(1059, 8), blk>>>(OFF_H3, 16, w3, w3, b3, b3,
                                         67735, 67735, 3);

    finalize_kernel<<<128, 256>>>(target, head_w, head_b, cluster_w, cluster_b,
                                  w1, b1, w2, b2, w3, b3, out);
}

// round 4
// speedup vs baseline: 1.5121x; 1.5121x over previous
#include <cuda_runtime.h>
#include <cuda_bf16.h>
#include <mma.h>

using namespace nvcuda;
typedef __nv_bfloat16 bf16;

#define OFF_H0 0
#define OFF_H1 1048576            // 1024*1024
#define OFF_H2 1310720            // +1024*256
#define OFF_H3 1376256            // +1024*64

// scratch (static device memory; no allocations anywhere)
__device__ bf16  g_H[1392640];
__device__ float g_sumexp[4096];

__global__ void zero_kernel() {
    int i = blockIdx.x * blockDim.x + threadIdx.x;
    if (i < 4096) g_sumexp[i] = 0.0f;
}

// ---------------------------------------------------------------------------
// exp-sum epilogue: warp owns a 32x32 C patch (ldm 32). lane = local row.
// Swizzled column order -> conflict-free smem reads. One atomic per lane.
// ---------------------------------------------------------------------------
__device__ __forceinline__ void exp_epilogue(const float* cp, const float* bias_s,
        int n0, int V, int wn, int lane, int row_g, int cidx)
{
    float s = 0.0f;
    #pragma unroll
    for (int c = 0; c < 32; c++) {
        int cc = (c + lane) & 31;
        int v = n0 + wn * 32 + cc;
        if (v < V) s += __expf(cp[lane * 32 + cc] + bias_s[wn * 32 + cc]);
    }
    atomicAdd(&g_sumexp[cidx * 1024 + row_g], s);
}

// ---------------------------------------------------------------------------
// vocab_small<K>: K in {16, 64}. Weight slab (64 x K) AND per-m-tile A fully
// resident; A double-buffered across m-tiles with register staging.
// smem: Bs[64*KP] | As0[128*KP] | As1[128*KP] | Cp[8*32*32 f32] | bias[64]
// ---------------------------------------------------------------------------
template<int K>
__global__ __launch_bounds__(256) void vocab_small_kernel(
        int h_off, const float* __restrict__ W, const float* __restrict__ bias,
        int V, int cidx)
{
    constexpr int KP = K + 8;
    constexpr int NV = (128 * K / 8) / 256;   // uint4 per thread per m-tile
    extern __shared__ char smem[];
    bf16*  Bs     = (bf16*)smem;
    bf16*  As0    = Bs + 64 * KP;
    bf16*  As1    = As0 + 128 * KP;
    float* Cp     = (float*)(As1 + 128 * KP);
    float* bias_s = Cp + 8 * 32 * 32;

    const int tid = threadIdx.x, warpId = tid >> 5, lane = tid & 31;
    const int wm = warpId & 3, wn = warpId >> 2;
    const int n0 = blockIdx.x * 64;
    const bf16* __restrict__ H = g_H + h_off;

    if (tid < 64) {
        int v = n0 + tid;
        bias_s[tid] = (v < V) ? bias[v] : 0.0f;
    }
    // weight slab, loaded & converted ONCE
    for (int idx = tid; idx < 64 * K / 4; idx += 256) {
        int r = idx / (K / 4), q = idx % (K / 4);
        int v = n0 + r;
        float4 val = make_float4(0.f, 0.f, 0.f, 0.f);
        if (v < V) val = *(const float4*)(W + (size_t)v * K + q * 4);
        __nv_bfloat162 lo = __floats2bfloat162_rn(val.x, val.y);
        __nv_bfloat162 hi = __floats2bfloat162_rn(val.z, val.w);
        uint2 pk; pk.x = *(unsigned*)&lo; pk.y = *(unsigned*)&hi;
        *(uint2*)(Bs + r * KP + q * 4) = pk;
    }

    uint4 st[NV];
    auto lda = [&](int m0) {
        #pragma unroll
        for (int i = 0; i < NV; i++) {
            int idx = tid + i * 256;
            int r = idx / (K / 8), q = idx % (K / 8);
            st[i] = *(const uint4*)(H + (size_t)(m0 + r) * K + q * 8);
        }
    };
    lda(0);
    __syncthreads();   // Bs + bias ready

    for (int mt = 0; mt < 8; mt++) {
        bf16* As = (mt & 1) ? As1 : As0;
        #pragma unroll
        for (int i = 0; i < NV; i++) {
            int idx = tid + i * 256;
            int r = idx / (K / 8), q = idx % (K / 8);
            *(uint4*)(As + r * KP + q * 8) = st[i];
        }
        __syncthreads();
        if (mt < 7) lda((mt + 1) * 128);   // LDGs overlap the mma below

        wmma::fragment<wmma::accumulator, 16, 16, 16, float> acc[2][2];
        #pragma unroll
        for (int i = 0; i < 2; i++)
            #pragma unroll
            for (int j = 0; j < 2; j++) wmma::fill_fragment(acc[i][j], 0.0f);

        #pragma unroll
        for (int kk = 0; kk < K; kk += 16) {
            wmma::fragment<wmma::matrix_a, 16, 16, 16, bf16, wmma::row_major> af[2];
            wmma::fragment<wmma::matrix_b, 16, 16, 16, bf16, wmma::col_major> bfr[2];
            #pragma unroll
            for (int i = 0; i < 2; i++)
                wmma::load_matrix_sync(af[i], As + (wm * 32 + i * 16) * KP + kk, KP);
            #pragma unroll
            for (int j = 0; j < 2; j++)
                wmma::load_matrix_sync(bfr[j], Bs + (wn * 32 + j * 16) * KP + kk, KP);
            #pragma unroll
            for (int i = 0; i < 2; i++)
                #pragma unroll
                for (int j = 0; j < 2; j++)
                    wmma::mma_sync(acc[i][j], af[i], bfr[j], acc[i][j]);
        }

        float* cp = Cp + warpId * 32 * 32;
        #pragma unroll
        for (int i = 0; i < 2; i++)
            #pragma unroll
            for (int j = 0; j < 2; j++)
                wmma::store_matrix_sync(cp + i * 16 * 32 + j * 16, acc[i][j], 32,
                                        wmma::mem_row_major);
        __syncwarp();
        exp_epilogue(cp, bias_s, n0, V, wn, lane, mt * 128 + wm * 32 + lane, cidx);
        // no block sync needed: next sts targets the other As buffer; Cp private.
    }
}

// ---------------------------------------------------------------------------
// vocab_big<K>: K in {256, 1024}. Weight slab resident; A streamed in 128-wide
// chunks, double-buffered, register-staged, ONE barrier per chunk.
// C patches reuse As0 (last chunk always consumes As1 -> race-free).
// smem: Bs[64*KP] | As0[128*136] | As1[128*136] | bias[64]
// ---------------------------------------------------------------------------
template<int K>
__global__ __launch_bounds__(256) void vocab_big_kernel(
        int h_off, const float* __restrict__ W, const float* __restrict__ W2,
        const float* __restrict__ bias, const float* __restrict__ bias2,
        int split, int V, int cidx)
{
    constexpr int KP  = K + 8;
    constexpr int NC  = K / 128;      // chunks per m-tile (even: 2 or 8)
    constexpr int APC = 136;
    extern __shared__ char smem[];
    bf16*  Bs     = (bf16*)smem;
    bf16*  As0    = Bs + 64 * KP;
    bf16*  As1    = As0 + 128 * APC;
    float* Cp     = (float*)As0;      // 8*32*32*4 = 32768 <= 34816 (As0 size)
    float* bias_s = (float*)(As1 + 128 * APC);

    const int tid = threadIdx.x, warpId = tid >> 5, lane = tid & 31;
    const int wm = warpId & 3, wn = warpId >> 2;
    const int n0 = blockIdx.x * 64;
    const bf16* __restrict__ H = g_H + h_off;

    if (tid < 64) {
        int v = n0 + tid;
        float bv = 0.0f;
        if (v < split)  bv = bias[v];
        else if (v < V) bv = bias2[v - split];
        bias_s[tid] = bv;
    }
    for (int idx = tid; idx < 64 * K / 4; idx += 256) {
        int r = idx / (K / 4), q = idx % (K / 4);
        int v = n0 + r;
        float4 val = make_float4(0.f, 0.f, 0.f, 0.f);
        if (v < split)  val = *(const float4*)(W + (size_t)v * K + q * 4);
        else if (v < V) val = *(const float4*)(W2 + (size_t)(v - split) * K + q * 4);
        __nv_bfloat162 lo = __floats2bfloat162_rn(val.x, val.y);
        __nv_bfloat162 hi = __floats2bfloat162_rn(val.z, val.w);
        uint2 pk; pk.x = *(unsigned*)&lo; pk.y = *(unsigned*)&hi;
        *(uint2*)(Bs + r * KP + q * 4) = pk;
    }

    uint4 st[8];
    auto lda = [&](int m0, int kc) {
        #pragma unroll
        for (int i = 0; i < 8; i++) {
            int idx = tid + i * 256;
            int r = idx >> 4, q = idx & 15;
            st[i] = *(const uint4*)(H + (size_t)(m0 + r) * K + kc * 128 + q * 8);
        }
    };
    lda(0, 0);
    __syncthreads();   // Bs + bias ready

    for (int mt = 0; mt < 8; mt++) {
        wmma::fragment<wmma::accumulator, 16, 16, 16, float> acc[2][2];
        #pragma unroll
        for (int i = 0; i < 2; i++)
            #pragma unroll
            for (int j = 0; j < 2; j++) wmma::fill_fragment(acc[i][j], 0.0f);

        for (int kc = 0; kc < NC; kc++) {
            bf16* As = (kc & 1) ? As1 : As0;
            #pragma unroll
            for (int i = 0; i < 8; i++) {
                int idx = tid + i * 256;
                int r = idx >> 4, q = idx & 15;
                *(uint4*)(As + r * APC + q * 8) = st[i];
            }
            __syncthreads();
            if (kc < NC - 1)      lda(mt * 128, kc + 1);
            else if (mt < 7)      lda((mt + 1) * 128, 0);

            #pragma unroll
            for (int kkl = 0; kkl < 128; kkl += 16) {
                wmma::fragment<wmma::matrix_a, 16, 16, 16, bf16, wmma::row_major> af[2];
                wmma::fragment<wmma::matrix_b, 16, 16, 16, bf16, wmma::col_major> bfr[2];
                #pragma unroll
                for (int i = 0; i < 2; i++)
                    wmma::load_matrix_sync(af[i], As + (wm * 32 + i * 16) * APC + kkl, APC);
                #pragma unroll
                for (int j = 0; j < 2; j++)
                    wmma::load_matrix_sync(bfr[j],
                        Bs + (wn * 32 + j * 16) * KP + kc * 128 + kkl, KP);
                #pragma unroll
                for (int i = 0; i < 2; i++)
                    #pragma unroll
                    for (int j = 0; j < 2; j++)
                        wmma::mma_sync(acc[i][j], af[i], bfr[j], acc[i][j]);
            }
        }
        // All warps are past sync(NC-1): every mma reading As0 (chunk NC-2) is
        // done; concurrent mma(NC-1) reads As1 only. Safe to write C into As0.
        float* cp = Cp + warpId * 32 * 32;
        #pragma unroll
        for (int i = 0; i < 2; i++)
            #pragma unroll
            for (int j = 0; j < 2; j++)
                wmma::store_matrix_sync(cp + i * 16 * 32 + j * 16, acc[i][j], 32,
                                        wmma::mem_row_major);
        __syncwarp();
        exp_epilogue(cp, bias_s, n0, V, wn, lane, mt * 128 + wm * 32 + lane, cidx);
        __syncthreads();   // epilogue reads done before next m-tile overwrites As0
    }
}

// ---------------------------------------------------------------------------
// Fused projection GEMM: 22 n-tiles across the 4 projections, 8 m-tiles.
// H[m,n] = sum_k hidden[m,k] * proj[k,n]; bf16 out to g_H.
// ---------------------------------------------------------------------------
#define AP 40
#define BPP 72
#define CP 68

__global__ __launch_bounds__(256) void proj_kernel(const float* __restrict__ A,
        const float* __restrict__ P0, const float* __restrict__ P1,
        const float* __restrict__ P2, const float* __restrict__ P3)
{
    __shared__ __align__(16) float s_c[128 * CP];
    bf16* As = (bf16*)s_c;
    bf16* Bs = As + 128 * AP;

    int bx = blockIdx.x;
    const float* B; int Nout, h_off, n0;
    if (bx < 16)       { B = P0; Nout = 1024; h_off = OFF_H0; n0 = bx * 64; }
    else if (bx < 20)  { B = P1; Nout = 256;  h_off = OFF_H1; n0 = (bx - 16) * 64; }
    else if (bx == 20) { B = P2; Nout = 64;   h_off = OFF_H2; n0 = 0; }
    else               { B = P3; Nout = 16;   h_off = OFF_H3; n0 = 0; }

    const int tid = threadIdx.x;
    const int warpId = tid >> 5;
    const int wm = warpId & 3, wn = warpId >> 2;
    const int m0 = blockIdx.y * 128;
    const int K = 1024;

    wmma::fragment<wmma::accumulator, 16, 16, 16, float> acc[2][2];
    #pragma unroll
    for (int i = 0; i < 2; i++)
        #pragma unroll
        for (int j = 0; j < 2; j++) wmma::fill_fragment(acc[i][j], 0.0f);

    for (int kt = 0; kt < K; kt += 32) {
        #pragma unroll
        for (int i = 0; i < 4; i++) {
            int idx = tid + i * 256;
            int r = idx >> 3, kq = (idx & 7) << 2;
            float4 v = *(const float4*)(A + (size_t)(m0 + r) * K + kt + kq);
            bf16* d = As + r * AP + kq;
            d[0] = __float2bfloat16(v.x); d[1] = __float2bfloat16(v.y);
            d[2] = __float2bfloat16(v.z); d[3] = __float2bfloat16(v.w);
        }
        #pragma unroll
        for (int i = 0; i < 2; i++) {
            int idx = tid + i * 256;
            int kr = idx >> 4, nq = (idx & 15) << 2;
            int n = n0 + nq;
            float4 v = make_float4(0.f, 0.f, 0.f, 0.f);
            if (n < Nout) v = *(const float4*)(B + (size_t)(kt + kr) * Nout + n);
            bf16* d = Bs + kr * BPP + nq;
            d[0] = __float2bfloat16(v.x); d[1] = __float2bfloat16(v.y);
            d[2] = __float2bfloat16(v.z); d[3] = __float2bfloat16(v.w);
        }
        __syncthreads();
        #pragma unroll
        for (int kk = 0; kk < 32; kk += 16) {
            wmma::fragment<wmma::matrix_a, 16, 16, 16, bf16, wmma::row_major> af[2];
            wmma::fragment<wmma::matrix_b, 16, 16, 16, bf16, wmma::row_major> bfr[2];
            #pragma unroll
            for (int i = 0; i < 2; i++)
                wmma::load_matrix_sync(af[i], As + (wm * 32 + i * 16) * AP + kk, AP);
            #pragma unroll
            for (int j = 0; j < 2; j++)
                wmma::load_matrix_sync(bfr[j], Bs + kk * BPP + wn * 32 + j * 16, BPP);
            #pragma unroll
            for (int i = 0; i < 2; i++)
                #pragma unroll
                for (int j = 0; j < 2; j++)
                    wmma::mma_sync(acc[i][j], af[i], bfr[j], acc[i][j]);
        }
        __syncthreads();
    }

    #pragma unroll
    for (int i = 0; i < 2; i++)
        #pragma unroll
        for (int j = 0; j < 2; j++)
            wmma::store_matrix_sync(s_c + (wm * 32 + i * 16) * CP + wn * 32 + j * 16,
                                    acc[i][j], CP, wmma::mem_row_major);
    __syncthreads();

    bf16* H = g_H + h_off;
    for (int idx = tid; idx < 128 * 64; idx += 256) {
        int r = idx >> 6, c = idx & 63;
        int n = n0 + c;
        if (n < Nout)
            H[(size_t)(m0 + r) * Nout + n] = __float2bfloat16(s_c[r * CP + c]);
    }
}

// ---------------------------------------------------------------------------
// Finalize: per-row target logit + combine with logsumexps. One warp per row.
// ---------------------------------------------------------------------------
__device__ __forceinline__ float wdot(const bf16* h, const float* w, int K, int lane) {
    float s = 0.0f;
    for (int k = lane; k < K; k += 32)
        s += __bfloat162float(h[k]) * w[k];
    #pragma unroll
    for (int o = 16; o; o >>= 1) s += __shfl_xor_sync(0xffffffffu, s, o);
    return s;
}

__global__ __launch_bounds__(256) void finalize_kernel(const int* __restrict__ target,
    const float* __restrict__ head_w,   const float* __restrict__ head_b,
    const float* __restrict__ cluster_w, const float* __restrict__ cluster_b,
    const float* __restrict__ w1, const float* __restrict__ b1,
    const float* __restrict__ w2, const float* __restrict__ b2,
    const float* __restrict__ w3, const float* __restrict__ b3,
    float* __restrict__ out)
{
    int warpId = threadIdx.x >> 5, lane = threadIdx.x & 31;
    int row = blockIdx.x * 8 + warpId;
    if (row >= 1024) return;

    const bf16* h0 = g_H + (size_t)row * 1024;

    float cl[3];
    #pragma unroll
    for (int j = 0; j < 3; j++)
        cl[j] = wdot(h0, cluster_w + j * 1024, 1024, lane) + cluster_b[j];

    float lse0 = logf(g_sumexp[row]);
    int t = target[row];
    float lp;
    if (t < 20000) {
        float s = wdot(h0, head_w + (size_t)t * 1024, 1024, lane) + head_b[t];
        lp = s - lse0;
    } else if (t < 40000) {
        int ti = t - 20000;
        const bf16* h = g_H + OFF_H1 + (size_t)row * 256;
        float s = wdot(h, w1 + (size_t)ti * 256, 256, lane) + b1[ti];
        lp = (cl[2] - lse0) + (s - logf(g_sumexp[1024 + row]));
    } else if (t < 200000) {
        int ti = t - 40000;
        const bf16* h = g_H + OFF_H2 + (size_t)row * 64;
        float s = wdot(h, w2 + (size_t)ti * 64, 64, lane) + b2[ti];
        lp = (cl[1] - lse0) + (s - logf(g_sumexp[2048 + row]));
    } else {
        int ti = t - 200000;
        const bf16* h = g_H + OFF_H3 + (size_t)row * 16;
        float s = wdot(h, w3 + (size_t)ti * 16, 16, lane) + b3[ti];
        lp = (cl[0] - lse0) + (s - logf(g_sumexp[3072 + row]));
    }
    if (lane == 0) out[row] = -lp;
}

// ---------------------------------------------------------------------------
extern "C" void kernel_launch(void* const* d_in, const int* in_sizes, int n_in,
                              void* d_out, int out_size)
{
    const float* hidden    = (const float*)d_in[0];
    const int*   target    = (const int*)  d_in[1];
    const float* head_w    = (const float*)d_in[2];
    const float* head_b    = (const float*)d_in[3];
    const float* cluster_w = (const float*)d_in[4];
    const float* cluster_b = (const float*)d_in[5];
    const float* proj0     = (const float*)d_in[6];
    const float* proj1     = (const float*)d_in[7];
    const float* proj2     = (const float*)d_in[8];
    const float* proj3     = (const float*)d_in[9];
    const float* w1        = (const float*)d_in[10];
    const float* b1        = (const float*)d_in[11];
    const float* w2        = (const float*)d_in[12];
    const float* b2        = (const float*)d_in[13];
    const float* w3        = (const float*)d_in[14];
    const float* b3        = (const float*)d_in[15];
    float* out = (float*)d_out;

    // dynamic smem sizes (bytes)
    const int SZ_HEAD = 64 * 1032 * 2 + 2 * 128 * 136 * 2 + 256;  // 201984
    const int SZ_T1   = 64 * 264 * 2  + 2 * 128 * 136 * 2 + 256;  // 103680
    const int SZ_T2   = 64 * 72 * 2 + 2 * 128 * 72 * 2 + 8 * 32 * 32 * 4 + 256;
    const int SZ_T3   = 64 * 24 * 2 + 2 * 128 * 24 * 2 + 8 * 32 * 32 * 4 + 256;

    static bool attr_done = false;
    if (!attr_done) {
        cudaFuncSetAttribute(vocab_big_kernel<1024>,
            cudaFuncAttributeMaxDynamicSharedMemorySize, SZ_HEAD);
        cudaFuncSetAttribute(vocab_big_kernel<256>,
            cudaFuncAttributeMaxDynamicSharedMemorySize, SZ_T1);
        cudaFuncSetAttribute(vocab_small_kernel<64>,
            cudaFuncAttributeMaxDynamicSharedMemorySize, SZ_T2);
        cudaFuncSetAttribute(vocab_small_kernel<16>,
            cudaFuncAttributeMaxDynamicSharedMemorySize, SZ_T3);
        attr_done = true;
    }

    dim3 blk(256);
    zero_kernel<<<16, 256>>>();

    proj_kernel<<<dim3(22, 8), blk>>>(hidden, proj0, proj1, proj2, proj3);

    vocab_big_kernel<1024><<<313, blk, SZ_HEAD>>>(OFF_H0, head_w, cluster_w,
                                                  head_b, cluster_b, 20000, 20003, 0);
    vocab_big_kernel<256><<<313, blk, SZ_T1>>>(OFF_H1, w1, w1, b1, b1,
                                               20000, 20000, 1);
    vocab_small_kernel<64><<<2500, blk, SZ_T2>>>(OFF_H2, w2, b2, 160000, 2);
    vocab_small_kernel<16><<<1059, blk, SZ_T3>>>(OFF_H3, w3, b3, 67735, 3);

    finalize_kernel<<<128, 256>>>(target, head_w, head_b, cluster_w, cluster_b,
                                  w1, b1, w2, b2, w3, b3, out);
}